// round 1
// baseline (speedup 1.0000x reference)
#include <cuda_runtime.h>
#include <cstdint>

#define D 512
#define HW (D * D)            // 262144 = 2^18
#define NB 32                 // batch
#define IMG_ELEMS ((size_t)NB * 3 * HW)
#define LO 0.001f
#define HI 510.999f           // D - 1.001

__device__ double g_loss_acc;

__global__ void vm_zero_kernel() {
    g_loss_acc = 0.0;
}

__device__ __forceinline__ void sample_branch(const float* __restrict__ img,  // [3, HW] for batch n
                                              float qx0, float qy0, float m,
                                              float r[3], float& loss) {
    float qx = fminf(fmaxf(qx0, LO), HI);
    float qy = fminf(fmaxf(qy0, LO), HI);
    float dx = qx0 - qx;
    float dy = qy0 - qy;
    loss += dx * dx + dy * dy;

    float fx = floorf(qx), cx = ceilf(qx);
    float fy = floorf(qy), cy = ceilf(qy);
    // weights: 1 - |q - nb|  (q >= fx, q <= cx after clip)
    float wfx = 1.0f - (qx - fx), wcx = 1.0f - (cx - qx);
    float wfy = 1.0f - (qy - fy), wcy = 1.0f - (cy - qy);

    int ifx = (int)fx, icx = (int)cx, ify = (int)fy, icy = (int)cy;
    // ind = y + D * x
    int i00 = ify + (ifx << 9);
    int i10 = ify + (icx << 9);
    int i01 = icy + (ifx << 9);
    int i11 = icy + (icx << 9);

    float wff = wfx * wfy;
    float wcf = wcx * wfy;
    float wfc = wfx * wcy;
    float wcc = wcx * wcy;

#pragma unroll
    for (int c = 0; c < 3; c++) {
        const float* ic = img + (size_t)c * HW;
        float v = wff * __ldg(ic + i00)
                + wcf * __ldg(ic + i10)
                + wfc * __ldg(ic + i01)
                + wcc * __ldg(ic + i11);
        r[c] += m * v;
    }
}

__global__ void __launch_bounds__(256) vm_main_kernel(
    const float* __restrict__ im1,
    const float* __restrict__ im2,
    const float* __restrict__ C,
    const float* __restrict__ M1,
    const float* __restrict__ M2,
    float* __restrict__ out) {

    int tid = blockIdx.x * blockDim.x + threadIdx.x;   // 0 .. NB*HW-1
    int n = tid >> 18;                                  // / HW
    int p = tid & (HW - 1);

    float x = (float)(p >> 9);      // row
    float y = (float)(p & 511);     // col

    const float* Cn = C + (size_t)n * 2 * HW;
    float c0 = __ldg(Cn + p);           // row-flow
    float c1 = __ldg(Cn + p + HW);      // col-flow
    float m1 = __ldg(M1 + (size_t)n * HW + p);
    float m2 = __ldg(M2 + (size_t)n * HW + p);

    float r[3] = {0.0f, 0.0f, 0.0f};
    float loss = 0.0f;

    const float* im1n = im1 + (size_t)n * 3 * HW;
    const float* im2n = im2 + (size_t)n * 3 * HW;

    // branch a: im1 sampled at q + C, masked by M1
    sample_branch(im1n, x + c0, y + c1, m1, r, loss);
    // branch b: im2 sampled at q - C, masked by M2
    sample_branch(im2n, x - c0, y - c1, m2, r, loss);

    size_t ob = (size_t)n * 3 * HW + p;
#pragma unroll
    for (int c = 0; c < 3; c++) {
        out[ob + (size_t)c * HW] = r[c];
    }

    // warp reduction of loss, one double atomic per warp
#pragma unroll
    for (int off = 16; off > 0; off >>= 1)
        loss += __shfl_down_sync(0xFFFFFFFFu, loss, off);
    if ((threadIdx.x & 31) == 0)
        atomicAdd(&g_loss_acc, (double)loss);
}

__global__ void vm_finalize_kernel(float* __restrict__ out) {
    // la + lb = (sum of both branches' clip residuals) / (N*2*HW) / (D*D) * 0.01
    double denom = (double)NB * 2.0 * (double)HW;
    double v = g_loss_acc / denom * (0.01 / (double)(D * D));
    out[IMG_ELEMS] = (float)v;
}

extern "C" void kernel_launch(void* const* d_in, const int* in_sizes, int n_in,
                              void* d_out, int out_size) {
    const float* im1 = (const float*)d_in[0];
    const float* im2 = (const float*)d_in[1];
    const float* C   = (const float*)d_in[2];
    const float* M1  = (const float*)d_in[3];
    const float* M2  = (const float*)d_in[4];
    float* out = (float*)d_out;

    vm_zero_kernel<<<1, 1>>>();

    int total = NB * HW;                  // 8,388,608 threads
    int threads = 256;
    int blocks = total / threads;         // 32768
    vm_main_kernel<<<blocks, threads>>>(im1, im2, C, M1, M2, out);

    if ((size_t)out_size > IMG_ELEMS) {
        vm_finalize_kernel<<<1, 1>>>(out);
    }
}

// round 2
// speedup vs baseline: 2.0018x; 2.0018x over previous
#include <cuda_runtime.h>
#include <cstdint>

#define D 512
#define HW (D * D)            // 262144 = 2^18
#define NB 32                 // batch
#define IMG_ELEMS ((size_t)NB * 3 * HW)
#define LO 0.001f
#define HI 510.999f           // D - 1.001

__device__ double g_loss_acc;

__global__ void vm_zero_kernel() {
    g_loss_acc = 0.0;
}

// One branch, one pixel. img points at batch-n's [3,HW] plane set.
__device__ __forceinline__ void sample_branch(const float* __restrict__ img,
                                              float qx0, float qy0, float m,
                                              float* __restrict__ r,  // r[0..2], stride 4
                                              float& loss) {
    float qx = fminf(fmaxf(qx0, LO), HI);
    float qy = fminf(fmaxf(qy0, LO), HI);
    float dx = qx0 - qx;
    float dy = qy0 - qy;
    loss += dx * dx + dy * dy;

    float fx = floorf(qx), cx = ceilf(qx);
    float fy = floorf(qy), cy = ceilf(qy);
    float wfx = 1.0f - (qx - fx), wcx = 1.0f - (cx - qx);
    float wfy = 1.0f - (qy - fy), wcy = 1.0f - (cy - qy);

    int ifx = (int)fx, icx = (int)cx, ify = (int)fy, icy = (int)cy;
    // ind = y + D * x
    int i00 = ify + (ifx << 9);
    int i10 = ify + (icx << 9);
    int i01 = icy + (ifx << 9);
    int i11 = icy + (icx << 9);

    float wff = wfx * wfy;
    float wcf = wcx * wfy;
    float wfc = wfx * wcy;
    float wcc = wcx * wcy;

#pragma unroll
    for (int c = 0; c < 3; c++) {
        const float* ic = img + (size_t)c * HW;
        float v = wff * __ldg(ic + i00)
                + wcf * __ldg(ic + i10)
                + wfc * __ldg(ic + i01)
                + wcc * __ldg(ic + i11);
        r[c * 4] += m * v;
    }
}

__global__ void __launch_bounds__(256) vm_main_kernel(
    const float* __restrict__ im1,
    const float* __restrict__ im2,
    const float* __restrict__ C,
    const float* __restrict__ M1,
    const float* __restrict__ M2,
    float* __restrict__ out) {

    int tid = blockIdx.x * blockDim.x + threadIdx.x;   // 0 .. NB*HW/4-1
    int idx4 = tid << 2;                                // first pixel of the 4
    int n = idx4 >> 18;                                 // / HW
    int p = idx4 & (HW - 1);                            // 4-aligned; all 4 px same row

    float x = (float)(p >> 9);       // row
    float yb = (float)(p & 511);     // first col of the 4

    const float* Cn = C + (size_t)n * 2 * HW;
    float4 c0v = *(const float4*)(Cn + p);          // row-flow
    float4 c1v = *(const float4*)(Cn + p + HW);     // col-flow
    float4 m1v = *(const float4*)(M1 + (size_t)n * HW + p);
    float4 m2v = *(const float4*)(M2 + (size_t)n * HW + p);

    const float* im1n = im1 + (size_t)n * 3 * HW;
    const float* im2n = im2 + (size_t)n * 3 * HW;

    // r[channel][pixel] flattened as r[c*4 + i]
    float r[12];
#pragma unroll
    for (int i = 0; i < 12; i++) r[i] = 0.0f;
    float loss = 0.0f;

    float c0a[4] = {c0v.x, c0v.y, c0v.z, c0v.w};
    float c1a[4] = {c1v.x, c1v.y, c1v.z, c1v.w};
    float m1a[4] = {m1v.x, m1v.y, m1v.z, m1v.w};
    float m2a[4] = {m2v.x, m2v.y, m2v.z, m2v.w};

#pragma unroll
    for (int i = 0; i < 4; i++) {
        float y = yb + (float)i;
        // branch a: im1 sampled at q + C, masked by M1
        sample_branch(im1n, x + c0a[i], y + c1a[i], m1a[i], &r[i], loss);
        // branch b: im2 sampled at q - C, masked by M2
        sample_branch(im2n, x - c0a[i], y - c1a[i], m2a[i], &r[i], loss);
    }

    size_t ob = (size_t)n * 3 * HW + p;
#pragma unroll
    for (int c = 0; c < 3; c++) {
        float4 o = make_float4(r[c * 4 + 0], r[c * 4 + 1], r[c * 4 + 2], r[c * 4 + 3]);
        *(float4*)(out + ob + (size_t)c * HW) = o;
    }

    // ---- loss reduction: warp shfl -> smem -> one atomic per block ----
#pragma unroll
    for (int off = 16; off > 0; off >>= 1)
        loss += __shfl_down_sync(0xFFFFFFFFu, loss, off);

    __shared__ float warp_part[8];   // 256 threads = 8 warps
    int wid = threadIdx.x >> 5;
    int lid = threadIdx.x & 31;
    if (lid == 0) warp_part[wid] = loss;
    __syncthreads();
    if (wid == 0) {
        float v = (lid < 8) ? warp_part[lid] : 0.0f;
#pragma unroll
        for (int off = 4; off > 0; off >>= 1)
            v += __shfl_down_sync(0xFFFFFFFFu, v, off);
        if (lid == 0)
            atomicAdd(&g_loss_acc, (double)v);
    }
}

__global__ void vm_finalize_kernel(float* __restrict__ out) {
    // la + lb = (sum of both branches' clip residuals) / (N*2*HW) / (D*D) * 0.01
    double denom = (double)NB * 2.0 * (double)HW;
    double v = g_loss_acc / denom * (0.01 / (double)(D * D));
    out[IMG_ELEMS] = (float)v;
}

extern "C" void kernel_launch(void* const* d_in, const int* in_sizes, int n_in,
                              void* d_out, int out_size) {
    const float* im1 = (const float*)d_in[0];
    const float* im2 = (const float*)d_in[1];
    const float* C   = (const float*)d_in[2];
    const float* M1  = (const float*)d_in[3];
    const float* M2  = (const float*)d_in[4];
    float* out = (float*)d_out;

    vm_zero_kernel<<<1, 1>>>();

    int total4 = (NB * HW) / 4;            // 2,097,152 threads
    int threads = 256;
    int blocks = total4 / threads;         // 8192
    vm_main_kernel<<<blocks, threads>>>(im1, im2, C, M1, M2, out);

    if ((size_t)out_size > IMG_ELEMS) {
        vm_finalize_kernel<<<1, 1>>>(out);
    }
}

// round 3
// speedup vs baseline: 4.3458x; 2.1709x over previous
#include <cuda_runtime.h>
#include <cstdint>

#define D 512
#define HW (D * D)            // 262144 = 2^18
#define NB 32                 // batch
#define IMG_ELEMS ((size_t)NB * 3 * HW)
#define LO 0.001f
#define HI 510.999f           // D - 1.001
#define NBLOCKS 8192          // (512/32)*(512/32)*32

__device__ float g_partials[NBLOCKS];

// One branch, one pixel. img points at batch-n's [3,HW] plane set.
// r stride 4 across channels (r[c*4]).
__device__ __forceinline__ void sample_branch(const float* __restrict__ img,
                                              float qx0, float qy0, float m,
                                              float* __restrict__ r,
                                              float& loss) {
    float qx = fminf(fmaxf(qx0, LO), HI);
    float qy = fminf(fmaxf(qy0, LO), HI);
    float dx = qx0 - qx;
    float dy = qy0 - qy;
    loss += dx * dx + dy * dy;

    float fx = floorf(qx), cx = ceilf(qx);
    float fy = floorf(qy), cy = ceilf(qy);
    float wfx = 1.0f - (qx - fx), wcx = 1.0f - (cx - qx);
    float wfy = 1.0f - (qy - fy), wcy = 1.0f - (cy - qy);

    int ifx = (int)fx, icx = (int)cx, ify = (int)fy, icy = (int)cy;
    // ind = y + D * x
    int i00 = ify + (ifx << 9);
    int i10 = ify + (icx << 9);
    int i01 = icy + (ifx << 9);
    int i11 = icy + (icx << 9);

    float wff = wfx * wfy;
    float wcf = wcx * wfy;
    float wfc = wfx * wcy;
    float wcc = wcx * wcy;

#pragma unroll
    for (int c = 0; c < 3; c++) {
        const float* ic = img + (size_t)c * HW;
        float v = wff * __ldg(ic + i00)
                + wcf * __ldg(ic + i10)
                + wfc * __ldg(ic + i01)
                + wcc * __ldg(ic + i11);
        r[c * 4] += m * v;
    }
}

// Tile mapping: block = 32x32 pixel tile of one batch image.
//   lane (0..31)  -> y within tile (consecutive columns: 1 cache-line column)
//   warp (0..7)   -> 4 consecutive rows (x) via ILP
__global__ void __launch_bounds__(256) vm_main_kernel(
    const float* __restrict__ im1,
    const float* __restrict__ im2,
    const float* __restrict__ C,
    const float* __restrict__ M1,
    const float* __restrict__ M2,
    float* __restrict__ out) {

    int bid = blockIdx.x;
    int ty = (bid & 15) << 5;           // tile y origin
    int tx = ((bid >> 4) & 15) << 5;    // tile x origin
    int n  = bid >> 8;                  // batch

    int lane = threadIdx.x & 31;
    int w    = threadIdx.x >> 5;

    int y  = ty + lane;                 // column, fixed per thread
    int x0 = tx + (w << 2);             // first of 4 rows

    const float* Cn  = C  + (size_t)n * 2 * HW;
    const float* M1n = M1 + (size_t)n * HW;
    const float* M2n = M2 + (size_t)n * HW;
    const float* im1n = im1 + (size_t)n * 3 * HW;
    const float* im2n = im2 + (size_t)n * 3 * HW;

    float yf = (float)y;

    float r[12];
#pragma unroll
    for (int i = 0; i < 12; i++) r[i] = 0.0f;
    float loss = 0.0f;

#pragma unroll
    for (int i = 0; i < 4; i++) {
        int x = x0 + i;
        int p = (x << 9) + y;
        float xf = (float)x;

        float c0 = __ldg(Cn + p);        // row-flow
        float c1 = __ldg(Cn + p + HW);   // col-flow
        float m1 = __ldg(M1n + p);
        float m2 = __ldg(M2n + p);

        // branch a: im1 sampled at q + C, masked by M1
        sample_branch(im1n, xf + c0, yf + c1, m1, &r[i], loss);
        // branch b: im2 sampled at q - C, masked by M2
        sample_branch(im2n, xf - c0, yf - c1, m2, &r[i], loss);
    }

    // stores: per row i, per channel c — warp-coalesced 128B each
#pragma unroll
    for (int i = 0; i < 4; i++) {
        int p = ((x0 + i) << 9) + y;
#pragma unroll
        for (int c = 0; c < 3; c++) {
            out[(size_t)n * 3 * HW + (size_t)c * HW + p] = r[c * 4 + i];
        }
    }

    // ---- loss reduction: warp shfl -> smem -> per-block partial ----
#pragma unroll
    for (int off = 16; off > 0; off >>= 1)
        loss += __shfl_down_sync(0xFFFFFFFFu, loss, off);

    __shared__ float warp_part[8];
    if (lane == 0) warp_part[w] = loss;
    __syncthreads();
    if (w == 0) {
        float v = (lane < 8) ? warp_part[lane] : 0.0f;
#pragma unroll
        for (int off = 4; off > 0; off >>= 1)
            v += __shfl_down_sync(0xFFFFFFFFu, v, off);
        if (lane == 0)
            g_partials[bid] = v;
    }
}

__global__ void __launch_bounds__(256) vm_finalize_kernel(float* __restrict__ out) {
    int t = threadIdx.x;
    float s = 0.0f;
    for (int i = t; i < NBLOCKS; i += 256)
        s += g_partials[i];
#pragma unroll
    for (int off = 16; off > 0; off >>= 1)
        s += __shfl_down_sync(0xFFFFFFFFu, s, off);
    __shared__ float warp_part[8];
    int w = t >> 5, lane = t & 31;
    if (lane == 0) warp_part[w] = s;
    __syncthreads();
    if (w == 0) {
        float v = (lane < 8) ? warp_part[lane] : 0.0f;
#pragma unroll
        for (int off = 4; off > 0; off >>= 1)
            v += __shfl_down_sync(0xFFFFFFFFu, v, off);
        if (lane == 0) {
            // la + lb = sum / (N*2*HW) / (D*D) * 0.01
            double denom = (double)NB * 2.0 * (double)HW;
            out[IMG_ELEMS] = (float)((double)v / denom * (0.01 / (double)(D * D)));
        }
    }
}

extern "C" void kernel_launch(void* const* d_in, const int* in_sizes, int n_in,
                              void* d_out, int out_size) {
    const float* im1 = (const float*)d_in[0];
    const float* im2 = (const float*)d_in[1];
    const float* C   = (const float*)d_in[2];
    const float* M1  = (const float*)d_in[3];
    const float* M2  = (const float*)d_in[4];
    float* out = (float*)d_out;

    vm_main_kernel<<<NBLOCKS, 256>>>(im1, im2, C, M1, M2, out);

    if ((size_t)out_size > IMG_ELEMS) {
        vm_finalize_kernel<<<1, 256>>>(out);
    }
}